// round 16
// baseline (speedup 1.0000x reference)
#include <cuda_runtime.h>

#define FRAME   160
#define ORDER   16
#define EPS     1e-8f
#define FPW     4                 // frames per warp
#define WARPS   4
#define THREADS (WARPS * 32)      // 128
#define FPB     (WARPS * FPW)     // 16 frames per block
#define FSTRIDE 198               // floats per frame region: 16 pad | 160 | 16 pad | 6 slack
#define PSTRIDE 99                // float2 pairs per frame region (odd -> conflict-free LDS.64)

typedef unsigned long long u64;

__device__ __forceinline__ u64 pack2(float lo, float hi) {
    u64 r; asm("mov.b64 %0, {%1, %2};" : "=l"(r) : "f"(lo), "f"(hi));
    return r;
}
#define BAR_SYNC(id)   asm volatile("bar.sync %0, %1;"   :: "r"(id), "r"(THREADS) : "memory")
#define BAR_ARRIVE(id) asm volatile("bar.arrive %0, %1;" :: "r"(id), "r"(THREADS) : "memory")

__global__ __launch_bounds__(THREADS, 8)
void lpc_residual_kernel(const float* __restrict__ x,
                         float* __restrict__ out,
                         int nframes)
{
    __shared__ __align__(16) float sx[WARPS * FPW * FSTRIDE];   // 12672 B
    __shared__ float rS[32][18];        // autocorr per frame; r[k] at [k] (even row -> LDS.64)
    __shared__ float aS[32][18];        // LPC coeffs per frame; a[k] at [k-1]

    const int lane   = threadIdx.x & 31;
    const int wid    = threadIdx.x >> 5;
    const int frame0 = blockIdx.x * FPB + wid * FPW;            // this warp's first frame

    float* sw  = sx + wid * FPW * FSTRIDE;
    u64*   swp = (u64*)sw;

    // ---- zero pads: per frame, floats [0,16) and [176,192) => pairs [0,8) and [88,96) ----
    {
        int f = lane >> 3, c = lane & 7;
        swp[f * PSTRIDE + c]      = 0ull;
        swp[f * PSTRIDE + 88 + c] = 0ull;
    }

    // ---- stage input: 10x LDG.64 + 10x STS.64 per lane, coalesced & conflict-free ----
    {
        const float2* gx2 = (const float2*)(x + (long long)frame0 * FRAME);
        #pragma unroll
        for (int q = 0; q < 10; q++) {
            int idx = q * 32 + lane;               // float2 index within warp's 320
            int f;
            if (q == 2)      f = (lane < 16) ? 0 : 1;   // frame boundary crossings
            else if (q == 7) f = (lane < 16) ? 2 : 3;
            else             f = (q * 32) / 80;         // compile-time constant
            if (frame0 + f < nframes) {
                float2 v = gx2[idx];
                // shared pair index: f*99 + 8 + (idx - 80f) = idx + 8 + 19f
                swp[idx + 8 + 19 * f] = pack2(v.x, v.y);
            }
        }
    }
    __syncwarp();   // warp only reads its own staged frames below

    const int fl = lane >> 3;               // frame within warp (0..3)
    const int p  = lane & 7;                // sub-lane within frame (0..7)
    const int myFrame = wid * FPW + fl;     // frame index within block
    // pair index of float w[0] = x[20p] of this frame (float idx fl*198 + 16 + 20p)
    const int ubase = fl * PSTRIDE + 8 + 10 * p;
    const float2* swp2 = (const float2*)swp;

    // ---- autocorr window w[0..35] via 18 LDS.64; w[0..19] stays live for the FIR ----
    float w[36];
    #pragma unroll
    for (int j = 0; j < 18; j++) {
        float2 t = swp2[ubase + j];
        w[2 * j] = t.x; w[2 * j + 1] = t.y;
    }

    // ---- autocorrelation with 4-lag fused butterfly:
    //   stage1 per lag; FSEL by p&1 folds lag pairs; stage2; FSEL by p&2; stage3.
    //   Lags k0..k0+3 land on lanes p=0..3 -> one predicated STS per group. ----
    const bool pi = (p & 1) != 0;
    const bool pj = (p & 2) != 0;
    #pragma unroll
    for (int g = 0; g < 4; g++) {
        const int k0 = 4 * g;
        float A0 = 0.f, A1 = 0.f, A2 = 0.f, A3 = 0.f;
        #pragma unroll
        for (int m = 0; m < 20; m++) {
            float wm = w[m];
            A0 = fmaf(wm, w[m + k0 + 0], A0);
            A1 = fmaf(wm, w[m + k0 + 1], A1);
            A2 = fmaf(wm, w[m + k0 + 2], A2);
            A3 = fmaf(wm, w[m + k0 + 3], A3);
        }
        A0 += __shfl_xor_sync(0xFFFFFFFFu, A0, 1);
        A1 += __shfl_xor_sync(0xFFFFFFFFu, A1, 1);
        A2 += __shfl_xor_sync(0xFFFFFFFFu, A2, 1);
        A3 += __shfl_xor_sync(0xFFFFFFFFu, A3, 1);
        float s = pi ? A1 : A0;                 // even lanes carry k0+0, odd k0+1
        float u = pi ? A3 : A2;                 // even lanes carry k0+2, odd k0+3
        s += __shfl_xor_sync(0xFFFFFFFFu, s, 2);
        u += __shfl_xor_sync(0xFFFFFFFFu, u, 2);
        float t = pj ? u : s;                   // lanes 0,1 -> s; lanes 2,3 -> u
        t += __shfl_xor_sync(0xFFFFFFFFu, t, 4);
        if (p < 4) rS[myFrame][k0 + p] = t;     // lane p holds r[k0+p]
    }
    {   // lag 16, classic butterfly
        float acc = 0.f;
        #pragma unroll
        for (int m = 0; m < 20; m++)
            acc = fmaf(w[m], w[m + 16], acc);
        acc += __shfl_xor_sync(0xFFFFFFFFu, acc, 1);
        acc += __shfl_xor_sync(0xFFFFFFFFu, acc, 2);
        acc += __shfl_xor_sync(0xFFFFFFFFu, acc, 4);
        if (p == 0) rS[myFrame][16] = acc;
    }

    if (wid == 0) {
        // ---- consumer: wait for all autocorrs, run Levinson (one frame per lane) ----
        BAR_SYNC(1);

        float rr[ORDER + 1];
        #pragma unroll
        for (int k = 0; k <= ORDER; k++)
            rr[k] = rS[lane][k];                // even row stride -> pairs vectorize

        float a[ORDER + 1];
        a[0] = 1.0f;
        float e = (rr[0] != 0.0f) ? rr[0] : EPS;
        #pragma unroll
        for (int i = 1; i <= ORDER; i++) {
            float s0 = 0.f, s1 = 0.f, s2 = 0.f, s3 = 0.f;
            #pragma unroll
            for (int j = 1; j < i; j++) {
                switch ((j - 1) & 3) {
                    case 0: s0 = fmaf(a[j], rr[i - j], s0); break;
                    case 1: s1 = fmaf(a[j], rr[i - j], s1); break;
                    case 2: s2 = fmaf(a[j], rr[i - j], s2); break;
                    default: s3 = fmaf(a[j], rr[i - j], s3); break;
                }
            }
            float acc = rr[i] - ((s0 + s1) + (s2 + s3));
            float kk = __fdividef(acc, e);
            float tn[ORDER + 1];
            #pragma unroll
            for (int j = 1; j < i; j++)
                tn[j] = fmaf(-kk, a[i - j], a[j]);
            #pragma unroll
            for (int j = 1; j < i; j++)
                a[j] = tn[j];
            a[i] = kk;
            e = fmaxf(fmaf(-kk, acc, e), EPS);   // e*(1-k^2) = e - k*acc
        }
        // coeff a[k] stored at column k-1 (even start -> 8x STS.64)
        #pragma unroll
        for (int k = 1; k <= ORDER; k++) aS[lane][k - 1] = a[k];

        BAR_ARRIVE(2);
        __syncwarp();       // make warp-0's own aS stores visible to its other lanes
    } else {
        BAR_ARRIVE(1);      // autocorrs published; don't wait for Levinson to start
    }

    // ---- history w[-16..-1] via 8 LDS.64 (prefetched under Levinson for warps 1-3);
    //      main window w[0..19] is already in registers from the autocorrelation ----
    float v[16];
    #pragma unroll
    for (int j = 0; j < 8; j++) {
        float2 t = swp2[ubase - 8 + j];
        v[2 * j] = t.x; v[2 * j + 1] = t.y;
    }

    if (wid != 0) BAR_SYNC(2);   // wait for coefficients

    // ---- broadcast coeffs (8-lane broadcast per frame; even column start -> LDS.64) ----
    float a[ORDER + 1];
    #pragma unroll
    for (int k = 1; k <= ORDER; k++) a[k] = aS[myFrame][k - 1];

    // ---- FIR: res[n] = w[n] + sum_{k=1}^{16} a[k] * w[n-k]; store as float4 groups ----
    const bool wr = (frame0 + fl) < nframes;
    float4* go4 = (float4*)(out + (long long)(frame0 + fl) * FRAME + 20 * p);

    #pragma unroll
    for (int g = 0; g < 5; g++) {
        float res[4];
        #pragma unroll
        for (int h = 0; h < 4; h++) {
            int m = 4 * g + h;
            float s = w[m];                    // a[0] = 1 term
            #pragma unroll
            for (int k = 1; k <= ORDER; k++) {
                int i = m - k;
                s = fmaf(a[k], (i >= 0) ? w[i] : v[16 + i], s);
            }
            res[h] = s;
        }
        if (wr) go4[g] = make_float4(res[0], res[1], res[2], res[3]);
    }
}

extern "C" void kernel_launch(void* const* d_in, const int* in_sizes, int n_in,
                              void* d_out, int out_size)
{
    const float* x = (const float*)d_in[0];
    float* out = (float*)d_out;

    long long total = in_sizes[0];
    int nframes = (int)(total / FRAME);                 // 128000 for the given shape
    int blocks  = (nframes + FPB - 1) / FPB;            // 8000

    lpc_residual_kernel<<<blocks, THREADS>>>(x, out, nframes);
}

// round 17
// speedup vs baseline: 1.0062x; 1.0062x over previous
#include <cuda_runtime.h>

#define FRAME   160
#define ORDER   16
#define EPS     1e-8f
#define FPW     4                 // frames per warp
#define WARPS   4
#define THREADS (WARPS * 32)      // 128
#define FPB     (WARPS * FPW)     // 16 frames per block
#define FSTRIDE 198               // floats per frame region: 16 pad | 160 | 16 pad | 6 slack
#define PSTRIDE 99                // float2 pairs per frame region (odd -> conflict-free LDS.64)

typedef unsigned long long u64;

__device__ __forceinline__ u64 pack2(float lo, float hi) {
    u64 r; asm("mov.b64 %0, {%1, %2};" : "=l"(r) : "f"(lo), "f"(hi));
    return r;
}
#define BAR_SYNC(id)   asm volatile("bar.sync %0, %1;"   :: "r"(id), "r"(THREADS) : "memory")
#define BAR_ARRIVE(id) asm volatile("bar.arrive %0, %1;" :: "r"(id), "r"(THREADS) : "memory")

__global__ __launch_bounds__(THREADS, 9)
void lpc_residual_kernel(const float* __restrict__ x,
                         float* __restrict__ out,
                         int nframes)
{
    __shared__ __align__(16) float sx[WARPS * FPW * FSTRIDE];   // 12672 B
    __shared__ float rS[32][18];        // autocorr per frame; r[k] at [k]
    __shared__ float aS[32][18];        // LPC coeffs per frame; a[k] at [k-1]

    const int lane   = threadIdx.x & 31;
    const int wid    = threadIdx.x >> 5;
    const int frame0 = blockIdx.x * FPB + wid * FPW;            // this warp's first frame

    float* sw  = sx + wid * FPW * FSTRIDE;
    u64*   swp = (u64*)sw;

    // ---- zero pads: per frame, floats [0,16) and [176,192) => pairs [0,8) and [88,96) ----
    {
        int f = lane >> 3, c = lane & 7;
        swp[f * PSTRIDE + c]      = 0ull;
        swp[f * PSTRIDE + 88 + c] = 0ull;
    }

    // ---- stage input: 10x LDG.64 + 10x STS.64 per lane, coalesced & conflict-free ----
    {
        const float2* gx2 = (const float2*)(x + (long long)frame0 * FRAME);
        #pragma unroll
        for (int q = 0; q < 10; q++) {
            int idx = q * 32 + lane;               // float2 index within warp's 320
            int f;
            if (q == 2)      f = (lane < 16) ? 0 : 1;   // frame boundary crossings
            else if (q == 7) f = (lane < 16) ? 2 : 3;
            else             f = (q * 32) / 80;         // compile-time constant
            if (frame0 + f < nframes) {
                float2 v = gx2[idx];
                // shared pair index: f*99 + 8 + (idx - 80f) = idx + 8 + 19f
                swp[idx + 8 + 19 * f] = pack2(v.x, v.y);
            }
        }
    }
    __syncwarp();   // warp only reads its own staged frames below

    const int fl = lane >> 3;               // frame within warp (0..3)
    const int p  = lane & 7;                // sub-lane within frame (0..7)
    const int myFrame = wid * FPW + fl;     // frame index within block
    // pair index of float w[0] = x[20p] of this frame (float idx fl*198 + 16 + 20p)
    const int ubase = fl * PSTRIDE + 8 + 10 * p;
    const float2* swp2 = (const float2*)swp;

    // ---- autocorr window w[0..35] via 18 LDS.64; w[0..19] stays live for the FIR ----
    float w[36];
    #pragma unroll
    for (int j = 0; j < 18; j++) {
        float2 t = swp2[ubase + j];
        w[2 * j] = t.x; w[2 * j + 1] = t.y;
    }

    // ---- autocorrelation with 4-lag fused butterfly:
    //   stage1 per lag; FSEL by p&1 folds lag pairs; stage2; FSEL by p&2; stage3.
    //   Lags k0..k0+3 land on lanes p=0..3 -> one predicated STS per group. ----
    const bool pi = (p & 1) != 0;
    const bool pj = (p & 2) != 0;
    #pragma unroll
    for (int g = 0; g < 4; g++) {
        const int k0 = 4 * g;
        float A0 = 0.f, A1 = 0.f, A2 = 0.f, A3 = 0.f;
        #pragma unroll
        for (int m = 0; m < 20; m++) {
            float wm = w[m];
            A0 = fmaf(wm, w[m + k0 + 0], A0);
            A1 = fmaf(wm, w[m + k0 + 1], A1);
            A2 = fmaf(wm, w[m + k0 + 2], A2);
            A3 = fmaf(wm, w[m + k0 + 3], A3);
        }
        A0 += __shfl_xor_sync(0xFFFFFFFFu, A0, 1);
        A1 += __shfl_xor_sync(0xFFFFFFFFu, A1, 1);
        A2 += __shfl_xor_sync(0xFFFFFFFFu, A2, 1);
        A3 += __shfl_xor_sync(0xFFFFFFFFu, A3, 1);
        float s = pi ? A1 : A0;                 // even lanes carry k0+0, odd k0+1
        float u = pi ? A3 : A2;                 // even lanes carry k0+2, odd k0+3
        s += __shfl_xor_sync(0xFFFFFFFFu, s, 2);
        u += __shfl_xor_sync(0xFFFFFFFFu, u, 2);
        float t = pj ? u : s;                   // lanes 0,1 -> s; lanes 2,3 -> u
        t += __shfl_xor_sync(0xFFFFFFFFu, t, 4);
        if (p < 4) rS[myFrame][k0 + p] = t;     // lane p holds r[k0+p]
    }
    {   // lag 16, classic butterfly
        float acc = 0.f;
        #pragma unroll
        for (int m = 0; m < 20; m++)
            acc = fmaf(w[m], w[m + 16], acc);
        acc += __shfl_xor_sync(0xFFFFFFFFu, acc, 1);
        acc += __shfl_xor_sync(0xFFFFFFFFu, acc, 2);
        acc += __shfl_xor_sync(0xFFFFFFFFu, acc, 4);
        if (p == 0) rS[myFrame][16] = acc;
    }

    if (wid == 0) {
        // ---- consumer: wait for all autocorrs, run Levinson (one frame per lane) ----
        BAR_SYNC(1);

        float rr[ORDER + 1];
        #pragma unroll
        for (int k = 0; k <= ORDER; k++)
            rr[k] = rS[lane][k];

        float a[ORDER + 1];
        a[0] = 1.0f;
        float e = (rr[0] != 0.0f) ? rr[0] : EPS;
        #pragma unroll
        for (int i = 1; i <= ORDER; i++) {
            float s0 = 0.f, s1 = 0.f, s2 = 0.f, s3 = 0.f;
            #pragma unroll
            for (int j = 1; j < i; j++) {
                switch ((j - 1) & 3) {
                    case 0: s0 = fmaf(a[j], rr[i - j], s0); break;
                    case 1: s1 = fmaf(a[j], rr[i - j], s1); break;
                    case 2: s2 = fmaf(a[j], rr[i - j], s2); break;
                    default: s3 = fmaf(a[j], rr[i - j], s3); break;
                }
            }
            float acc = rr[i] - ((s0 + s1) + (s2 + s3));
            float kk = __fdividef(acc, e);
            float tn[ORDER + 1];
            #pragma unroll
            for (int j = 1; j < i; j++)
                tn[j] = fmaf(-kk, a[i - j], a[j]);
            #pragma unroll
            for (int j = 1; j < i; j++)
                a[j] = tn[j];
            a[i] = kk;
            e = fmaxf(fmaf(-kk, acc, e), EPS);   // e*(1-k^2) = e - k*acc
        }
        // coeff a[k] stored at column k-1
        #pragma unroll
        for (int k = 1; k <= ORDER; k++) aS[lane][k - 1] = a[k];

        BAR_ARRIVE(2);
        __syncwarp();       // make warp-0's own aS stores visible to its other lanes
    } else {
        BAR_ARRIVE(1);      // autocorrs published; don't wait for Levinson to start
    }

    // ---- history w[-16..-1] via 8 LDS.64 (prefetched under Levinson for warps 1-3);
    //      main window w[0..19] is already in registers from the autocorrelation ----
    float v[16];
    #pragma unroll
    for (int j = 0; j < 8; j++) {
        float2 t = swp2[ubase - 8 + j];
        v[2 * j] = t.x; v[2 * j + 1] = t.y;
    }

    if (wid != 0) BAR_SYNC(2);   // wait for coefficients

    // ---- broadcast coeffs (8-lane broadcast per frame, conflict-free) ----
    float a[ORDER + 1];
    #pragma unroll
    for (int k = 1; k <= ORDER; k++) a[k] = aS[myFrame][k - 1];

    // ---- FIR: res[n] = w[n] + sum_{k=1}^{16} a[k] * w[n-k]; store as float4 groups ----
    const bool wr = (frame0 + fl) < nframes;
    float4* go4 = (float4*)(out + (long long)(frame0 + fl) * FRAME + 20 * p);

    #pragma unroll
    for (int g = 0; g < 5; g++) {
        float res[4];
        #pragma unroll
        for (int h = 0; h < 4; h++) {
            int m = 4 * g + h;
            float s = w[m];                    // a[0] = 1 term
            #pragma unroll
            for (int k = 1; k <= ORDER; k++) {
                int i = m - k;
                s = fmaf(a[k], (i >= 0) ? w[i] : v[16 + i], s);
            }
            res[h] = s;
        }
        if (wr) go4[g] = make_float4(res[0], res[1], res[2], res[3]);
    }
}

extern "C" void kernel_launch(void* const* d_in, const int* in_sizes, int n_in,
                              void* d_out, int out_size)
{
    const float* x = (const float*)d_in[0];
    float* out = (float*)d_out;

    long long total = in_sizes[0];
    int nframes = (int)(total / FRAME);                 // 128000 for the given shape
    int blocks  = (nframes + FPB - 1) / FPB;            // 8000

    lpc_residual_kernel<<<blocks, THREADS>>>(x, out, nframes);
}